// round 1
// baseline (speedup 1.0000x reference)
#include <cuda_runtime.h>
#include <math.h>

#define B_ 256
#define N_ 2048
#define M_ 64
#define H_ 512
#define R_ 2
#define IN_ 128
#define OUT_ 128
#define EPS_ 1e-8f

// d_out float offsets (tuple flattened in order: out, reads, h, c, weights, new_mem)
#define OFF_OUT   0
#define OFF_READS 32768
#define OFF_H     65536
#define OFF_C     196608
#define OFF_W     327680
#define OFF_MEM   1900544

// scratch (allocation-free rule: __device__ globals)
__device__ float g_xcat[B_ * 768];    // [b][ inp(128) | prev_reads r-major(128) | prev_h(512) ]
__device__ float g_gates[B_ * 2048];  // LSTM pre-activations
__device__ float g_p[B_ * 352];       // head params: cols 0..69 read0, 70..139 read1, 140..337 write (incl e,a)

__device__ __forceinline__ float sigf(float x) { return 1.0f / (1.0f + expf(-x)); }
__device__ __forceinline__ float softplusf(float x) { return fmaxf(x, 0.0f) + log1pf(expf(-fabsf(x))); }

// ---------------- K0: pack [x, prev_h] ----------------
__global__ void k0_pack(const float* __restrict__ inp,
                        const float* __restrict__ prev_reads,
                        const float* __restrict__ prev_h) {
    int idx = blockIdx.x * 256 + threadIdx.x;  // 256*768
    int b = idx / 768, col = idx - b * 768;
    float v;
    if (col < 128) {
        v = inp[b * 128 + col];
    } else if (col < 256) {
        int r = (col - 128) >> 6, m = (col - 128) & 63;
        v = prev_reads[(r * B_ + b) * 64 + m];
    } else {
        v = prev_h[b * 512 + (col - 256)];
    }
    g_xcat[idx] = v;
}

// ---------------- K1: gates GEMM: gates[b][j] = sum_k xcat[b][k] * Wcat[j][k] ----------------
__global__ void __launch_bounds__(256) k1_gates(const float* __restrict__ Wih,
                                                const float* __restrict__ Whh) {
    __shared__ float As[16][68];
    __shared__ float Ws[16][68];
    int tid = threadIdx.x;
    int j0 = blockIdx.x * 64, b0 = blockIdx.y * 64;
    int tx = tid & 15, ty = tid >> 4;
    int lrow = tid >> 2, lk4 = (tid & 3) * 4;
    float acc[4][4] = {};
    for (int kt = 0; kt < 48; kt++) {
        int kb = kt * 16;
        float4 av = *(const float4*)(g_xcat + (b0 + lrow) * 768 + kb + lk4);
        As[lk4 + 0][lrow] = av.x; As[lk4 + 1][lrow] = av.y;
        As[lk4 + 2][lrow] = av.z; As[lk4 + 3][lrow] = av.w;
        int kg = kb + lk4;
        const float* wp = (kg < 256) ? (Wih + (j0 + lrow) * 256 + kg)
                                     : (Whh + (j0 + lrow) * 512 + (kg - 256));
        float4 wv = *(const float4*)wp;
        Ws[lk4 + 0][lrow] = wv.x; Ws[lk4 + 1][lrow] = wv.y;
        Ws[lk4 + 2][lrow] = wv.z; Ws[lk4 + 3][lrow] = wv.w;
        __syncthreads();
#pragma unroll
        for (int kk = 0; kk < 16; kk++) {
            float4 a4 = *(const float4*)&As[kk][ty * 4];
            float4 b4 = *(const float4*)&Ws[kk][tx * 4];
            float ar[4] = {a4.x, a4.y, a4.z, a4.w};
            float br[4] = {b4.x, b4.y, b4.z, b4.w};
#pragma unroll
            for (int i = 0; i < 4; i++)
#pragma unroll
                for (int j = 0; j < 4; j++) acc[i][j] = fmaf(ar[i], br[j], acc[i][j]);
        }
        __syncthreads();
    }
#pragma unroll
    for (int i = 0; i < 4; i++)
#pragma unroll
        for (int j = 0; j < 4; j++)
            g_gates[(b0 + ty * 4 + i) * 2048 + j0 + tx * 4 + j] = acc[i][j];
}

// ---------------- K1b: LSTM elementwise ----------------
__global__ void k1b_lstm(const float* __restrict__ blstm,
                         const float* __restrict__ prev_c,
                         float* __restrict__ dout) {
    int idx = blockIdx.x * 256 + threadIdx.x;  // B*H
    int b = idx >> 9, hh = idx & 511;
    const float* gr = g_gates + b * 2048;
    float gi = gr[hh] + blstm[hh];
    float gf = gr[512 + hh] + blstm[512 + hh];
    float gg = gr[1024 + hh] + blstm[1024 + hh];
    float go = gr[1536 + hh] + blstm[1536 + hh];
    float c = sigf(gf) * prev_c[idx] + sigf(gi) * tanhf(gg);
    float h = sigf(go) * tanhf(c);
    dout[OFF_C + idx] = c;
    dout[OFF_H + idx] = h;
}

// ---------------- K2: head-param GEMM: P[b][col] = sum_h h[b][h] * W[col][h] + bias ----------------
__global__ void __launch_bounds__(256) k2_p(const float* __restrict__ readW,
                                            const float* __restrict__ readb,
                                            const float* __restrict__ writeW,
                                            const float* __restrict__ writeb,
                                            const float* __restrict__ dout) {
    __shared__ float Hs[16][34];
    __shared__ float Ws2[16][34];
    int tid = threadIdx.x;
    int c0 = blockIdx.x * 32, b0 = blockIdx.y * 32;
    int tx = tid & 15, ty = tid >> 4;
    int lr = tid >> 3, lk = (tid & 7) * 2;
    int col_l = c0 + lr;
    const float* wrow = 0;
    if (col_l < 140) wrow = readW + col_l * 512;
    else if (col_l < 338) wrow = writeW + (col_l - 140) * 512;
    float acc[2][2] = {};
    for (int kt = 0; kt < 32; kt++) {
        int kb = kt * 16;
        float2 hv = *(const float2*)(dout + OFF_H + (b0 + lr) * 512 + kb + lk);
        Hs[lk][lr] = hv.x; Hs[lk + 1][lr] = hv.y;
        float2 wv = make_float2(0.f, 0.f);
        if (wrow) wv = *(const float2*)(wrow + kb + lk);
        Ws2[lk][lr] = wv.x; Ws2[lk + 1][lr] = wv.y;
        __syncthreads();
#pragma unroll
        for (int kk = 0; kk < 16; kk++) {
            float h0 = Hs[kk][ty * 2], h1 = Hs[kk][ty * 2 + 1];
            float w0 = Ws2[kk][tx * 2], w1 = Ws2[kk][tx * 2 + 1];
            acc[0][0] = fmaf(h0, w0, acc[0][0]); acc[0][1] = fmaf(h0, w1, acc[0][1]);
            acc[1][0] = fmaf(h1, w0, acc[1][0]); acc[1][1] = fmaf(h1, w1, acc[1][1]);
        }
        __syncthreads();
    }
#pragma unroll
    for (int i = 0; i < 2; i++)
#pragma unroll
        for (int j = 0; j < 2; j++) {
            int col = c0 + tx * 2 + j;
            if (col < 338) {
                float bias = (col < 140) ? readb[col] : writeb[col - 140];
                g_p[(b0 + ty * 2 + i) * 352 + col] = acc[i][j] + bias;
            }
        }
}

// ---------------- block reductions (512 threads, 16 warps) ----------------
__device__ __forceinline__ float blk_red_sum(float v, volatile float* red) {
    int lane = threadIdx.x & 31, w = threadIdx.x >> 5;
#pragma unroll
    for (int o = 16; o; o >>= 1) v += __shfl_xor_sync(0xffffffffu, v, o);
    if (lane == 0) red[w] = v;
    __syncthreads();
    if (w == 0) {
        float x = (lane < 16) ? red[lane] : 0.0f;
#pragma unroll
        for (int o = 8; o; o >>= 1) x += __shfl_xor_sync(0xffffffffu, x, o);
        if (lane == 0) red[0] = x;
    }
    __syncthreads();
    float r = red[0];
    __syncthreads();
    return r;
}
__device__ __forceinline__ float blk_red_max(float v, volatile float* red) {
    int lane = threadIdx.x & 31, w = threadIdx.x >> 5;
#pragma unroll
    for (int o = 16; o; o >>= 1) v = fmaxf(v, __shfl_xor_sync(0xffffffffu, v, o));
    if (lane == 0) red[w] = v;
    __syncthreads();
    if (w == 0) {
        float x = (lane < 16) ? red[lane] : -3.0e38f;
#pragma unroll
        for (int o = 8; o; o >>= 1) x = fmaxf(x, __shfl_xor_sync(0xffffffffu, x, o));
        if (lane == 0) red[0] = x;
    }
    __syncthreads();
    float r = red[0];
    __syncthreads();
    return r;
}

// ---------------- K3: addressing (one block per b) ----------------
__global__ void __launch_bounds__(512, 1) k3_address(const float* __restrict__ mem,
                                                     const float* __restrict__ prev_ws,
                                                     float* __restrict__ dout) {
    __shared__ float sim_s[3 * 2048];
    __shared__ float wgs[2048];
    __shared__ float ksm[3 * 64];
    __shared__ float red[16];
    __shared__ float hp[3][6];
    int b = blockIdx.x;
    int tid = threadIdx.x;
    int lane = tid & 31, wrp = tid >> 5;
    const float* Pb = g_p + b * 352;

    if (tid < 192) {
        int h = tid >> 6, m = tid & 63;
        int base = (h < 2) ? h * 70 : 140;
        ksm[h * 64 + m] = tanhf(Pb[base + m]);
    }
    if (tid < 3) {
        int h = tid;
        int base = (h < 2) ? h * 70 : 140;
        float p64 = Pb[base + 64], p65 = Pb[base + 65];
        float q0 = Pb[base + 66], q1 = Pb[base + 67], q2 = Pb[base + 68];
        float p69 = Pb[base + 69];
        hp[h][0] = softplusf(p64);            // beta
        hp[h][1] = sigf(p65);                 // g
        float mx = fmaxf(q0, fmaxf(q1, q2));
        float e0 = expf(q0 - mx), e1 = expf(q1 - mx), e2 = expf(q2 - mx);
        float si = 1.0f / (e0 + e1 + e2);
        hp[h][2] = e0 * si; hp[h][3] = e1 * si; hp[h][4] = e2 * si;  // s
        hp[h][5] = 1.0f + softplusf(p69);     // gamma
    }
    __syncthreads();

    int q = lane >> 2, s = lane & 3, m0 = s * 16;
    float kreg[3][16];
#pragma unroll
    for (int h = 0; h < 3; h++)
#pragma unroll
        for (int i = 0; i < 16; i++) kreg[h][i] = ksm[h * 64 + m0 + i];
    float kn[3];
#pragma unroll
    for (int h = 0; h < 3; h++) {
        float sq = 0.f;
#pragma unroll
        for (int i = 0; i < 16; i++) sq = fmaf(kreg[h][i], kreg[h][i], sq);
        sq += __shfl_xor_sync(0xffffffffu, sq, 1);
        sq += __shfl_xor_sync(0xffffffffu, sq, 2);
        kn[h] = sqrtf(sq);
    }

    const float* mb = mem + (size_t)b * N_ * M_;
    for (int it = 0; it < 16; it++) {
        int n = it * 128 + wrp * 8 + q;
        const float4* rp4 = (const float4*)(mb + n * 64 + m0);
        float xv[16];
#pragma unroll
        for (int c = 0; c < 4; c++) {
            float4 v = rp4[c];
            xv[c * 4 + 0] = v.x; xv[c * 4 + 1] = v.y; xv[c * 4 + 2] = v.z; xv[c * 4 + 3] = v.w;
        }
        float d0 = 0.f, d1 = 0.f, d2 = 0.f, ss = 0.f;
#pragma unroll
        for (int i = 0; i < 16; i++) {
            float x = xv[i];
            d0 = fmaf(kreg[0][i], x, d0);
            d1 = fmaf(kreg[1][i], x, d1);
            d2 = fmaf(kreg[2][i], x, d2);
            ss = fmaf(x, x, ss);
        }
        d0 += __shfl_xor_sync(0xffffffffu, d0, 1); d0 += __shfl_xor_sync(0xffffffffu, d0, 2);
        d1 += __shfl_xor_sync(0xffffffffu, d1, 1); d1 += __shfl_xor_sync(0xffffffffu, d1, 2);
        d2 += __shfl_xor_sync(0xffffffffu, d2, 1); d2 += __shfl_xor_sync(0xffffffffu, d2, 2);
        ss += __shfl_xor_sync(0xffffffffu, ss, 1); ss += __shfl_xor_sync(0xffffffffu, ss, 2);
        if (s == 0) {
            float mn = sqrtf(ss);
            sim_s[0 * 2048 + n] = d0 / (kn[0] * mn + EPS_);
            sim_s[1 * 2048 + n] = d1 / (kn[1] * mn + EPS_);
            sim_s[2 * 2048 + n] = d2 / (kn[2] * mn + EPS_);
        }
    }
    __syncthreads();

    for (int h = 0; h < 3; h++) {
        float beta = hp[h][0], g = hp[h][1];
        float s0 = hp[h][2], s1 = hp[h][3], s2 = hp[h][4], gamma = hp[h][5];
        float z[4], lm = -3.0e38f;
#pragma unroll
        for (int j = 0; j < 4; j++) {
            int n = tid + j * 512;
            z[j] = beta * sim_s[h * 2048 + n];
            lm = fmaxf(lm, z[j]);
        }
        float mx = blk_red_max(lm, red);
        float ex[4], lsum = 0.f;
#pragma unroll
        for (int j = 0; j < 4; j++) { ex[j] = expf(z[j] - mx); lsum += ex[j]; }
        float S = blk_red_sum(lsum, red);
        float invS = 1.0f / S;
        const float* pwb = prev_ws + ((size_t)h * B_ + b) * N_;
#pragma unroll
        for (int j = 0; j < 4; j++) {
            int n = tid + j * 512;
            float wc = ex[j] * invS;
            wgs[n] = fmaf(g, wc, (1.0f - g) * pwb[n]);
        }
        __syncthreads();
        float wp4[4], psum = 0.f;
#pragma unroll
        for (int j = 0; j < 4; j++) {
            int n = tid + j * 512;
            float wt = s0 * wgs[(n + 2047) & 2047] + s1 * wgs[n] + s2 * wgs[(n + 1) & 2047];
            wp4[j] = powf(wt + EPS_, gamma);
            psum += wp4[j];
        }
        float S2 = blk_red_sum(psum, red);
        float inv2 = 1.0f / (S2 + EPS_);
        float* wout = dout + OFF_W + ((size_t)h * B_ + b) * N_;
#pragma unroll
        for (int j = 0; j < 4; j++) {
            int n = tid + j * 512;
            wout[n] = wp4[j] * inv2;
        }
        __syncthreads();
    }
}

// ---------------- K4: reads + memory write (one block per b) ----------------
__global__ void __launch_bounds__(512) k4_readwrite(const float* __restrict__ mem,
                                                    float* __restrict__ dout) {
    __shared__ float ws_s[3 * 2048];
    __shared__ float es[64], as_[64];
    int b = blockIdx.x, tid = threadIdx.x;
    int lane = tid & 31, wrp = tid >> 5;
    for (int idx = tid; idx < 6144; idx += 512) {
        int h = idx >> 11, n = idx & 2047;
        ws_s[idx] = dout[OFF_W + (size_t)h * B_ * N_ + (size_t)b * N_ + n];
    }
    if (tid < 64) es[tid] = sigf(g_p[b * 352 + 210 + tid]);
    else if (tid < 128) as_[tid - 64] = g_p[b * 352 + 274 + (tid - 64)];
    __syncthreads();

    int m2 = lane * 2;
    float e0 = es[m2], e1 = es[m2 + 1], a0 = as_[m2], a1 = as_[m2 + 1];
    float r00 = 0.f, r01 = 0.f, r10 = 0.f, r11 = 0.f;
#pragma unroll 4
    for (int i = 0; i < 128; i++) {
        int n = wrp * 128 + i;
        const float2* src = (const float2*)(mem + ((size_t)b * N_ + n) * M_);
        float2 v = src[lane];
        float w0 = ws_s[n], w1 = ws_s[2048 + n], ww = ws_s[4096 + n];
        float f0 = fmaf(-ww, e0, 1.0f), f1 = fmaf(-ww, e1, 1.0f);
        float2 nv;
        nv.x = fmaf(v.x, f0, ww * a0);
        nv.y = fmaf(v.y, f1, ww * a1);
        ((float2*)(dout + OFF_MEM + ((size_t)b * N_ + n) * M_))[lane] = nv;
        r00 = fmaf(w0, v.x, r00); r01 = fmaf(w0, v.y, r01);
        r10 = fmaf(w1, v.x, r10); r11 = fmaf(w1, v.y, r11);
    }
    __syncthreads();
    ws_s[wrp * 64 + m2] = r00; ws_s[wrp * 64 + m2 + 1] = r01;
    ws_s[1024 + wrp * 64 + m2] = r10; ws_s[1024 + wrp * 64 + m2 + 1] = r11;
    __syncthreads();
    if (tid < 128) {
        int h = tid >> 6, m = tid & 63;
        float sum = 0.f;
#pragma unroll
        for (int w = 0; w < 16; w++) sum += ws_s[h * 1024 + w * 64 + m];
        dout[OFF_READS + h * B_ * M_ + b * M_ + m] = sum;
    }
}

// ---------------- K5: output GEMM + sigmoid ----------------
__global__ void __launch_bounds__(256) k5_out(const float* __restrict__ outW,
                                              const float* __restrict__ outb,
                                              float* __restrict__ dout) {
    __shared__ float xs[8 * 648];
    int tid = threadIdx.x, b0 = blockIdx.x * 8;
    for (int idx = tid; idx < 8 * 640; idx += 256) {
        int bb = idx / 640, k = idx - bb * 640;
        int b = b0 + bb;
        float v;
        if (k < 512) v = dout[OFF_H + b * 512 + k];
        else if (k < 576) v = dout[OFF_READS + b * 64 + (k - 512)];
        else v = dout[OFF_READS + B_ * M_ + b * 64 + (k - 576)];
        xs[bb * 648 + k] = v;
    }
    __syncthreads();
    int o = tid & 127, g2 = tid >> 7;
    float acc[4] = {0.f, 0.f, 0.f, 0.f};
    const float4* w4 = (const float4*)(outW + o * 640);
    for (int k4 = 0; k4 < 160; k4++) {
        float4 wv = w4[k4];
#pragma unroll
        for (int j = 0; j < 4; j++) {
            float4 x = *(const float4*)&xs[(g2 + 2 * j) * 648 + k4 * 4];
            acc[j] = fmaf(wv.x, x.x, fmaf(wv.y, x.y, fmaf(wv.z, x.z, fmaf(wv.w, x.w, acc[j]))));
        }
    }
    float bo = outb[o];
#pragma unroll
    for (int j = 0; j < 4; j++)
        dout[OFF_OUT + (b0 + g2 + 2 * j) * 128 + o] = sigf(acc[j] + bo);
}

extern "C" void kernel_launch(void* const* d_in, const int* in_sizes, int n_in,
                              void* d_out, int out_size) {
    const float* inp        = (const float*)d_in[0];
    const float* prev_reads = (const float*)d_in[1];
    const float* prev_h     = (const float*)d_in[2];
    const float* prev_c     = (const float*)d_in[3];
    const float* prev_ws    = (const float*)d_in[4];
    const float* memory     = (const float*)d_in[5];
    const float* W_ih       = (const float*)d_in[6];
    const float* W_hh       = (const float*)d_in[7];
    const float* b_lstm     = (const float*)d_in[8];
    const float* read_W     = (const float*)d_in[9];
    const float* read_b     = (const float*)d_in[10];
    const float* write_W    = (const float*)d_in[11];
    const float* write_b    = (const float*)d_in[12];
    const float* out_W      = (const float*)d_in[13];
    const float* out_b      = (const float*)d_in[14];
    float* dout = (float*)d_out;

    k0_pack<<<768, 256>>>(inp, prev_reads, prev_h);
    k1_gates<<<dim3(32, 4), 256>>>(W_ih, W_hh);
    k1b_lstm<<<512, 256>>>(b_lstm, prev_c, dout);
    k2_p<<<dim3(11, 8), 256>>>(read_W, read_b, write_W, write_b, dout);
    k3_address<<<256, 512>>>(memory, prev_ws, dout);
    k4_readwrite<<<256, 512>>>(memory, dout);
    k5_out<<<32, 256>>>(out_W, out_b, dout);
}

// round 2
// speedup vs baseline: 1.3237x; 1.3237x over previous
#include <cuda_runtime.h>
#include <math.h>
#include <stdint.h>

#define B_ 256
#define N_ 2048
#define M_ 64
#define H_ 512
#define EPS_ 1e-8f

// d_out float offsets: out, reads, h, c, weights, new_mem
#define OFF_OUT   0
#define OFF_READS 32768
#define OFF_H     65536
#define OFF_C     196608
#define OFF_W     327680
#define OFF_MEM   1900544

__device__ float g_xcat[B_ * 768];
__device__ float g_gates[B_ * 2048];
__device__ float g_p[B_ * 352];

__device__ __forceinline__ float sigf(float x) { return 1.0f / (1.0f + expf(-x)); }
__device__ __forceinline__ float softplusf(float x) { return fmaxf(x, 0.0f) + log1pf(expf(-fabsf(x))); }

union U64F2 { unsigned long long u; float2 f; };
__device__ __forceinline__ void ffma2(unsigned long long& d, unsigned long long a, unsigned long long b) {
    asm("fma.rn.f32x2 %0, %1, %2, %0;" : "+l"(d) : "l"(a), "l"(b));
}

// ---------------- K0: pack [x, prev_reads, prev_h] ----------------
__global__ void k0_pack(const float* __restrict__ inp,
                        const float* __restrict__ prev_reads,
                        const float* __restrict__ prev_h) {
    int idx = blockIdx.x * 256 + threadIdx.x;
    int b = idx / 768, col = idx - b * 768;
    float v;
    if (col < 128) v = inp[b * 128 + col];
    else if (col < 256) {
        int r = (col - 128) >> 6, m = (col - 128) & 63;
        v = prev_reads[(r * B_ + b) * 64 + m];
    } else v = prev_h[b * 512 + (col - 256)];
    g_xcat[idx] = v;
}

// ---------------- K1: gates GEMM with f32x2 packed FMA + sw pipeline ----------------
__global__ void __launch_bounds__(256) k1_gates(const float* __restrict__ Wih,
                                                const float* __restrict__ Whh) {
    __shared__ float As2[32][132];   // duplicated A: [kk][2*row + {0,1}], 16B-aligned rows
    __shared__ float Ws[32][68];     // [kk][jrow]
    int tid = threadIdx.x;
    int j0 = blockIdx.x * 64, b0 = blockIdx.y * 64;
    int tx = tid & 15, ty = tid >> 4;
    int lrow = tid >> 2, lk8 = (tid & 3) * 8;
    const float* arow = g_xcat + (b0 + lrow) * 768;
    const float* wih = Wih + (j0 + lrow) * 256;
    const float* whh = Whh + (j0 + lrow) * 512;

    unsigned long long acc[4][2];
#pragma unroll
    for (int i = 0; i < 4; i++) { acc[i][0] = 0ull; acc[i][1] = 0ull; }

    float4 pa0, pa1, pw0, pw1;
    {
        pa0 = *(const float4*)(arow + lk8);
        pa1 = *(const float4*)(arow + lk8 + 4);
        int kg0 = lk8, kg1 = lk8 + 4;
        pw0 = *(const float4*)((kg0 < 256) ? (wih + kg0) : (whh + kg0 - 256));
        pw1 = *(const float4*)((kg1 < 256) ? (wih + kg1) : (whh + kg1 - 256));
    }
    for (int kt = 0; kt < 24; kt++) {
#pragma unroll
        for (int i = 0; i < 4; i++) {
            float v0 = (&pa0.x)[i], v1 = (&pa1.x)[i];
            As2[lk8 + i][2 * lrow] = v0;     As2[lk8 + i][2 * lrow + 1] = v0;
            As2[lk8 + 4 + i][2 * lrow] = v1; As2[lk8 + 4 + i][2 * lrow + 1] = v1;
            Ws[lk8 + i][lrow] = (&pw0.x)[i];
            Ws[lk8 + 4 + i][lrow] = (&pw1.x)[i];
        }
        __syncthreads();
        if (kt + 1 < 24) {
            int kb = (kt + 1) * 32;
            pa0 = *(const float4*)(arow + kb + lk8);
            pa1 = *(const float4*)(arow + kb + lk8 + 4);
            int kg0 = kb + lk8, kg1 = kb + lk8 + 4;
            pw0 = *(const float4*)((kg0 < 256) ? (wih + kg0) : (whh + kg0 - 256));
            pw1 = *(const float4*)((kg1 < 256) ? (wih + kg1) : (whh + kg1 - 256));
        }
#pragma unroll
        for (int kk = 0; kk < 32; kk++) {
            ulonglong2 a01 = *(const ulonglong2*)&As2[kk][ty * 8];
            ulonglong2 a23 = *(const ulonglong2*)&As2[kk][ty * 8 + 4];
            ulonglong2 bb  = *(const ulonglong2*)&Ws[kk][tx * 4];
            ffma2(acc[0][0], a01.x, bb.x); ffma2(acc[0][1], a01.x, bb.y);
            ffma2(acc[1][0], a01.y, bb.x); ffma2(acc[1][1], a01.y, bb.y);
            ffma2(acc[2][0], a23.x, bb.x); ffma2(acc[2][1], a23.x, bb.y);
            ffma2(acc[3][0], a23.y, bb.x); ffma2(acc[3][1], a23.y, bb.y);
        }
        __syncthreads();
    }
#pragma unroll
    for (int i = 0; i < 4; i++) {
        U64F2 u0, u1; u0.u = acc[i][0]; u1.u = acc[i][1];
        *(float4*)&g_gates[(b0 + ty * 4 + i) * 2048 + j0 + tx * 4] =
            make_float4(u0.f.x, u0.f.y, u1.f.x, u1.f.y);
    }
}

// ---------------- K1b: LSTM elementwise ----------------
__global__ void k1b_lstm(const float* __restrict__ blstm,
                         const float* __restrict__ prev_c,
                         float* __restrict__ dout) {
    int idx = blockIdx.x * 256 + threadIdx.x;
    int b = idx >> 9, hh = idx & 511;
    const float* gr = g_gates + b * 2048;
    float gi = gr[hh] + blstm[hh];
    float gf = gr[512 + hh] + blstm[512 + hh];
    float gg = gr[1024 + hh] + blstm[1024 + hh];
    float go = gr[1536 + hh] + blstm[1536 + hh];
    float c = sigf(gf) * prev_c[idx] + sigf(gi) * tanhf(gg);
    float h = sigf(go) * tanhf(c);
    dout[OFF_C + idx] = c;
    dout[OFF_H + idx] = h;
}

// ---------------- K2: head-param GEMM, k-tile 64 + sw pipeline ----------------
__global__ void __launch_bounds__(256) k2_p(const float* __restrict__ readW,
                                            const float* __restrict__ readb,
                                            const float* __restrict__ writeW,
                                            const float* __restrict__ writeb,
                                            const float* __restrict__ dout) {
    __shared__ float Hst[64][34];
    __shared__ float Wst[64][34];
    int tid = threadIdx.x;
    int c0 = blockIdx.x * 32, b0 = blockIdx.y * 32;
    int tx = tid & 15, ty = tid >> 4;
    int lr = tid >> 3, lk8 = (tid & 7) * 8;
    const float* hrow = dout + OFF_H + (b0 + lr) * 512;
    int col_l = c0 + lr;
    const float* wrow = 0;
    if (col_l < 140) wrow = readW + col_l * 512;
    else if (col_l < 338) wrow = writeW + (col_l - 140) * 512;

    float acc[2][2] = {};
    float4 ph0, ph1, pw0, pw1;
    ph0 = *(const float4*)(hrow + lk8);
    ph1 = *(const float4*)(hrow + lk8 + 4);
    pw0 = wrow ? *(const float4*)(wrow + lk8) : make_float4(0.f, 0.f, 0.f, 0.f);
    pw1 = wrow ? *(const float4*)(wrow + lk8 + 4) : make_float4(0.f, 0.f, 0.f, 0.f);

    for (int kt = 0; kt < 8; kt++) {
#pragma unroll
        for (int i = 0; i < 4; i++) {
            Hst[lk8 + i][lr] = (&ph0.x)[i];
            Hst[lk8 + 4 + i][lr] = (&ph1.x)[i];
            Wst[lk8 + i][lr] = (&pw0.x)[i];
            Wst[lk8 + 4 + i][lr] = (&pw1.x)[i];
        }
        __syncthreads();
        if (kt + 1 < 8) {
            int kb = (kt + 1) * 64;
            ph0 = *(const float4*)(hrow + kb + lk8);
            ph1 = *(const float4*)(hrow + kb + lk8 + 4);
            pw0 = wrow ? *(const float4*)(wrow + kb + lk8) : make_float4(0.f, 0.f, 0.f, 0.f);
            pw1 = wrow ? *(const float4*)(wrow + kb + lk8 + 4) : make_float4(0.f, 0.f, 0.f, 0.f);
        }
#pragma unroll
        for (int kk = 0; kk < 64; kk++) {
            float2 h2 = *(const float2*)&Hst[kk][ty * 2];
            float2 w2 = *(const float2*)&Wst[kk][tx * 2];
            acc[0][0] = fmaf(h2.x, w2.x, acc[0][0]); acc[0][1] = fmaf(h2.x, w2.y, acc[0][1]);
            acc[1][0] = fmaf(h2.y, w2.x, acc[1][0]); acc[1][1] = fmaf(h2.y, w2.y, acc[1][1]);
        }
        __syncthreads();
    }
#pragma unroll
    for (int i = 0; i < 2; i++)
#pragma unroll
        for (int j = 0; j < 2; j++) {
            int col = c0 + tx * 2 + j;
            if (col < 338) {
                float bias = (col < 140) ? readb[col] : writeb[col - 140];
                g_p[(b0 + ty * 2 + i) * 352 + col] = acc[i][j] + bias;
            }
        }
}

// ---------------- block reductions (512 threads) ----------------
__device__ __forceinline__ float blk_red_sum(float v, volatile float* red) {
    int lane = threadIdx.x & 31, w = threadIdx.x >> 5;
#pragma unroll
    for (int o = 16; o; o >>= 1) v += __shfl_xor_sync(0xffffffffu, v, o);
    if (lane == 0) red[w] = v;
    __syncthreads();
    if (w == 0) {
        float x = (lane < 16) ? red[lane] : 0.0f;
#pragma unroll
        for (int o = 8; o; o >>= 1) x += __shfl_xor_sync(0xffffffffu, x, o);
        if (lane == 0) red[0] = x;
    }
    __syncthreads();
    float r = red[0];
    __syncthreads();
    return r;
}
__device__ __forceinline__ float blk_red_max(float v, volatile float* red) {
    int lane = threadIdx.x & 31, w = threadIdx.x >> 5;
#pragma unroll
    for (int o = 16; o; o >>= 1) v = fmaxf(v, __shfl_xor_sync(0xffffffffu, v, o));
    if (lane == 0) red[w] = v;
    __syncthreads();
    if (w == 0) {
        float x = (lane < 16) ? red[lane] : -3.0e38f;
#pragma unroll
        for (int o = 8; o; o >>= 1) x = fmaxf(x, __shfl_xor_sync(0xffffffffu, x, o));
        if (lane == 0) red[0] = x;
    }
    __syncthreads();
    float r = red[0];
    __syncthreads();
    return r;
}

// ---------------- K34: fused addressing + read/write (one block per b) ----------------
__global__ void __launch_bounds__(512) k34_fused(const float* __restrict__ mem,
                                                 const float* __restrict__ prev_ws,
                                                 float* __restrict__ dout) {
    __shared__ float sim_s[3 * 2048];   // sims, then reused as final weights
    __shared__ float wgs[2048];         // gated weights, then partial-read buffer
    __shared__ float ksm[3 * 64];
    __shared__ float red[16];
    __shared__ float hp[3][6];
    __shared__ __align__(16) float es[64];
    __shared__ __align__(16) float as_[64];
    int b = blockIdx.x;
    int tid = threadIdx.x;
    int lane = tid & 31, wrp = tid >> 5;
    const float* Pb = g_p + b * 352;

    if (tid < 192) {
        int h = tid >> 6, m = tid & 63;
        int base = (h < 2) ? h * 70 : 140;
        ksm[h * 64 + m] = tanhf(Pb[base + m]);
    } else if (tid >= 320 && tid < 384) {
        es[tid - 320] = sigf(Pb[210 + (tid - 320)]);
    } else if (tid >= 384 && tid < 448) {
        as_[tid - 384] = Pb[274 + (tid - 384)];
    }
    if (tid < 3) {
        int h = tid;
        int base = (h < 2) ? h * 70 : 140;
        float q0 = Pb[base + 66], q1 = Pb[base + 67], q2 = Pb[base + 68];
        hp[h][0] = softplusf(Pb[base + 64]);
        hp[h][1] = sigf(Pb[base + 65]);
        float mx = fmaxf(q0, fmaxf(q1, q2));
        float e0 = expf(q0 - mx), e1 = expf(q1 - mx), e2 = expf(q2 - mx);
        float si = 1.0f / (e0 + e1 + e2);
        hp[h][2] = e0 * si; hp[h][3] = e1 * si; hp[h][4] = e2 * si;
        hp[h][5] = 1.0f + softplusf(Pb[base + 69]);
    }
    __syncthreads();

    // ---- phase B: stream memory, compute cosine sims (unroll 2) ----
    int q = lane >> 2, s = lane & 3, m0 = s * 16;
    float kreg[3][16];
#pragma unroll
    for (int h = 0; h < 3; h++)
#pragma unroll
        for (int i = 0; i < 16; i++) kreg[h][i] = ksm[h * 64 + m0 + i];
    float kn[3];
#pragma unroll
    for (int h = 0; h < 3; h++) {
        float sq = 0.f;
#pragma unroll
        for (int i = 0; i < 16; i++) sq = fmaf(kreg[h][i], kreg[h][i], sq);
        sq += __shfl_xor_sync(0xffffffffu, sq, 1);
        sq += __shfl_xor_sync(0xffffffffu, sq, 2);
        kn[h] = sqrtf(sq);
    }

    const float* mb = mem + (size_t)b * N_ * M_;
    for (int it = 0; it < 16; it += 2) {
        int na = it * 128 + wrp * 8 + q;
        int nb2 = na + 128;
        const float4* ra = (const float4*)(mb + na * 64 + m0);
        const float4* rb = (const float4*)(mb + nb2 * 64 + m0);
        float4 va[4], vb[4];
#pragma unroll
        for (int c = 0; c < 4; c++) va[c] = ra[c];
#pragma unroll
        for (int c = 0; c < 4; c++) vb[c] = rb[c];
#pragma unroll
        for (int half = 0; half < 2; half++) {
            float4* vv = half ? vb : va;
            int n = half ? nb2 : na;
            float d0 = 0.f, d1 = 0.f, d2 = 0.f, ss = 0.f;
#pragma unroll
            for (int c = 0; c < 4; c++) {
#pragma unroll
                for (int j = 0; j < 4; j++) {
                    float x = (&vv[c].x)[j];
                    int i = c * 4 + j;
                    d0 = fmaf(kreg[0][i], x, d0);
                    d1 = fmaf(kreg[1][i], x, d1);
                    d2 = fmaf(kreg[2][i], x, d2);
                    ss = fmaf(x, x, ss);
                }
            }
            d0 += __shfl_xor_sync(0xffffffffu, d0, 1); d0 += __shfl_xor_sync(0xffffffffu, d0, 2);
            d1 += __shfl_xor_sync(0xffffffffu, d1, 1); d1 += __shfl_xor_sync(0xffffffffu, d1, 2);
            d2 += __shfl_xor_sync(0xffffffffu, d2, 1); d2 += __shfl_xor_sync(0xffffffffu, d2, 2);
            ss += __shfl_xor_sync(0xffffffffu, ss, 1); ss += __shfl_xor_sync(0xffffffffu, ss, 2);
            if (s == 0) {
                float mn = sqrtf(ss);
                sim_s[0 * 2048 + n] = d0 / (kn[0] * mn + EPS_);
                sim_s[1 * 2048 + n] = d1 / (kn[1] * mn + EPS_);
                sim_s[2 * 2048 + n] = d2 / (kn[2] * mn + EPS_);
            }
        }
    }
    __syncthreads();

    // ---- phase C: softmax / interpolate / shift / sharpen ----
    for (int h = 0; h < 3; h++) {
        float beta = hp[h][0], g = hp[h][1];
        float s0 = hp[h][2], s1 = hp[h][3], s2 = hp[h][4], gamma = hp[h][5];
        float z[4], lm = -3.0e38f;
#pragma unroll
        for (int j = 0; j < 4; j++) {
            int n = tid + j * 512;
            z[j] = beta * sim_s[h * 2048 + n];
            lm = fmaxf(lm, z[j]);
        }
        float mx = blk_red_max(lm, red);
        float ex[4], lsum = 0.f;
#pragma unroll
        for (int j = 0; j < 4; j++) { ex[j] = expf(z[j] - mx); lsum += ex[j]; }
        float S = blk_red_sum(lsum, red);
        float invS = 1.0f / S;
        const float* pwb = prev_ws + ((size_t)h * B_ + b) * N_;
#pragma unroll
        for (int j = 0; j < 4; j++) {
            int n = tid + j * 512;
            wgs[n] = fmaf(g, ex[j] * invS, (1.0f - g) * pwb[n]);
        }
        __syncthreads();
        float wp4[4], psum = 0.f;
#pragma unroll
        for (int j = 0; j < 4; j++) {
            int n = tid + j * 512;
            float wt = s0 * wgs[(n + 2047) & 2047] + s1 * wgs[n] + s2 * wgs[(n + 1) & 2047];
            wp4[j] = powf(wt + EPS_, gamma);
            psum += wp4[j];
        }
        float S2 = blk_red_sum(psum, red);
        float inv2 = 1.0f / (S2 + EPS_);
        float* wout = dout + OFF_W + ((size_t)h * B_ + b) * N_;
#pragma unroll
        for (int j = 0; j < 4; j++) {
            int n = tid + j * 512;
            float wv = wp4[j] * inv2;
            wout[n] = wv;
            sim_s[h * 2048 + n] = wv;   // keep weights in smem for phase D
        }
        __syncthreads();
    }

    // ---- phase D: memory write + weighted reads (float4, unroll 4) ----
    int hl = lane >> 4, lm = lane & 15;
    float4 e4 = *(const float4*)&es[lm * 4];
    float4 a4 = *(const float4*)&as_[lm * 4];
    float racc0[4] = {0.f, 0.f, 0.f, 0.f};
    float racc1[4] = {0.f, 0.f, 0.f, 0.f};
    const float4* msrc = (const float4*)(mem + (size_t)b * N_ * M_);
    float4* mdst = (float4*)(dout + OFF_MEM + (size_t)b * N_ * M_);

    for (int i = 0; i < 64; i += 4) {
        float4 v[4]; float w0[4], w1[4], ww[4]; int nn[4];
#pragma unroll
        for (int u = 0; u < 4; u++) {
            int n = wrp * 128 + 2 * (i + u) + hl;
            nn[u] = n;
            v[u] = msrc[n * 16 + lm];
            w0[u] = sim_s[n]; w1[u] = sim_s[2048 + n]; ww[u] = sim_s[4096 + n];
        }
#pragma unroll
        for (int u = 0; u < 4; u++) {
            float4 nv;
            nv.x = fmaf(v[u].x, fmaf(-ww[u], e4.x, 1.0f), ww[u] * a4.x);
            nv.y = fmaf(v[u].y, fmaf(-ww[u], e4.y, 1.0f), ww[u] * a4.y);
            nv.z = fmaf(v[u].z, fmaf(-ww[u], e4.z, 1.0f), ww[u] * a4.z);
            nv.w = fmaf(v[u].w, fmaf(-ww[u], e4.w, 1.0f), ww[u] * a4.w);
            mdst[nn[u] * 16 + lm] = nv;
            racc0[0] = fmaf(w0[u], v[u].x, racc0[0]);
            racc0[1] = fmaf(w0[u], v[u].y, racc0[1]);
            racc0[2] = fmaf(w0[u], v[u].z, racc0[2]);
            racc0[3] = fmaf(w0[u], v[u].w, racc0[3]);
            racc1[0] = fmaf(w1[u], v[u].x, racc1[0]);
            racc1[1] = fmaf(w1[u], v[u].y, racc1[1]);
            racc1[2] = fmaf(w1[u], v[u].z, racc1[2]);
            racc1[3] = fmaf(w1[u], v[u].w, racc1[3]);
        }
    }
#pragma unroll
    for (int u = 0; u < 4; u++) {
        racc0[u] += __shfl_xor_sync(0xffffffffu, racc0[u], 16);
        racc1[u] += __shfl_xor_sync(0xffffffffu, racc1[u], 16);
    }
    __syncthreads();   // wgs free for reuse
    if (lane < 16) {
#pragma unroll
        for (int u = 0; u < 4; u++) {
            wgs[wrp * 128 + lm * 4 + u] = racc0[u];
            wgs[wrp * 128 + 64 + lm * 4 + u] = racc1[u];
        }
    }
    __syncthreads();
    if (tid < 128) {
        int h = tid >> 6, m = tid & 63;
        float sum = 0.f;
#pragma unroll
        for (int w = 0; w < 16; w++) sum += wgs[w * 128 + h * 64 + m];
        dout[OFF_READS + h * B_ * M_ + b * M_ + m] = sum;
    }
}

// ---------------- K5: output GEMM + sigmoid (SMEM-tiled W, 128 blocks) ----------------
__global__ void __launch_bounds__(256) k5_out(const float* __restrict__ outW,
                                              const float* __restrict__ outb,
                                              float* __restrict__ dout) {
    __shared__ float Wst[128][68];      // [o][k-within-tile]
    __shared__ float xs[2][644];
    int tid = threadIdx.x;
    int b0 = blockIdx.x * 2;
    int o = tid & 127, dup = tid >> 7;
    int lr = tid >> 1, c8 = (tid & 1) * 32;

    for (int idx = tid; idx < 2 * 640; idx += 256) {
        int bb = idx / 640, k = idx - bb * 640;
        int b = b0 + bb;
        float v;
        if (k < 512) v = dout[OFF_H + b * 512 + k];
        else if (k < 576) v = dout[OFF_READS + b * 64 + (k - 512)];
        else v = dout[OFF_READS + B_ * M_ + b * 64 + (k - 576)];
        xs[bb][k] = v;
    }

    float acc = 0.f;
    float4 pw[8];
#pragma unroll
    for (int i = 0; i < 8; i++) pw[i] = *(const float4*)(outW + lr * 640 + c8 + 4 * i);
    for (int kt = 0; kt < 10; kt++) {
        __syncthreads();
#pragma unroll
        for (int i = 0; i < 8; i++) *(float4*)&Wst[lr][c8 + 4 * i] = pw[i];
        __syncthreads();
        if (kt + 1 < 10) {
            int kb = (kt + 1) * 64;
#pragma unroll
            for (int i = 0; i < 8; i++) pw[i] = *(const float4*)(outW + lr * 640 + kb + c8 + 4 * i);
        }
        int kb = kt * 64;
#pragma unroll
        for (int k4 = 0; k4 < 16; k4++) {
            float4 wv = *(const float4*)&Wst[o][k4 * 4];
            float4 xv = *(const float4*)&xs[dup][kb + k4 * 4];
            acc = fmaf(wv.x, xv.x, acc);
            acc = fmaf(wv.y, xv.y, acc);
            acc = fmaf(wv.z, xv.z, acc);
            acc = fmaf(wv.w, xv.w, acc);
        }
    }
    dout[OFF_OUT + (b0 + dup) * 128 + o] = sigf(acc + outb[o]);
}

extern "C" void kernel_launch(void* const* d_in, const int* in_sizes, int n_in,
                              void* d_out, int out_size) {
    const float* inp        = (const float*)d_in[0];
    const float* prev_reads = (const float*)d_in[1];
    const float* prev_h     = (const float*)d_in[2];
    const float* prev_c     = (const float*)d_in[3];
    const float* prev_ws    = (const float*)d_in[4];
    const float* memory     = (const float*)d_in[5];
    const float* W_ih       = (const float*)d_in[6];
    const float* W_hh       = (const float*)d_in[7];
    const float* b_lstm     = (const float*)d_in[8];
    const float* read_W     = (const float*)d_in[9];
    const float* read_b     = (const float*)d_in[10];
    const float* write_W    = (const float*)d_in[11];
    const float* write_b    = (const float*)d_in[12];
    const float* out_W      = (const float*)d_in[13];
    const float* out_b      = (const float*)d_in[14];
    float* dout = (float*)d_out;

    k0_pack<<<768, 256>>>(inp, prev_reads, prev_h);
    k1_gates<<<dim3(32, 4), 256>>>(W_ih, W_hh);
    k1b_lstm<<<512, 256>>>(b_lstm, prev_c, dout);
    k2_p<<<dim3(11, 8), 256>>>(read_W, read_b, write_W, write_b, dout);
    k34_fused<<<256, 512>>>(memory, prev_ws, dout);
    k5_out<<<128, 256>>>(out_W, out_b, dout);
}

// round 3
// speedup vs baseline: 1.5661x; 1.1831x over previous
#include <cuda_runtime.h>
#include <math.h>
#include <stdint.h>

#define B_ 256
#define N_ 2048
#define M_ 64
#define H_ 512
#define EPS_ 1e-8f

// d_out float offsets: out, reads, h, c, weights, new_mem
#define OFF_OUT   0
#define OFF_READS 32768
#define OFF_H     65536
#define OFF_C     196608
#define OFF_W     327680
#define OFF_MEM   1900544

__device__ float g_xcat[B_ * 768];
__device__ float g_gates4[4 * B_ * 2048];   // split-k partials for gates
__device__ float g_p4[4 * B_ * 352];        // split-k partials for head params

__device__ __forceinline__ float sigf(float x) { return 1.0f / (1.0f + expf(-x)); }
__device__ __forceinline__ float softplusf(float x) { return fmaxf(x, 0.0f) + log1pf(expf(-fabsf(x))); }

union U64F2 { unsigned long long u; float2 f; };
__device__ __forceinline__ void ffma2(unsigned long long& d, unsigned long long a, unsigned long long b) {
    asm("fma.rn.f32x2 %0, %1, %2, %0;" : "+l"(d) : "l"(a), "l"(b));
}

// ---------------- K0: pack [x, prev_reads, prev_h] ----------------
__global__ void k0_pack(const float* __restrict__ inp,
                        const float* __restrict__ prev_reads,
                        const float* __restrict__ prev_h) {
    int idx = blockIdx.x * 256 + threadIdx.x;
    int b = idx / 768, col = idx - b * 768;
    float v;
    if (col < 128) v = inp[b * 128 + col];
    else if (col < 256) {
        int r = (col - 128) >> 6, m = (col - 128) & 63;
        v = prev_reads[(r * B_ + b) * 64 + m];
    } else v = prev_h[b * 512 + (col - 256)];
    g_xcat[idx] = v;
}

// ---------------- K1: gates GEMM, k-pair f32x2, split-k=4 ----------------
// tile: 64 b x 128 j, thread 4x8 (j interleaved by 16), k-slab 16, double buffered
__global__ void __launch_bounds__(256, 2) k1_gates(const float* __restrict__ Wih,
                                                   const float* __restrict__ Whh) {
    __shared__ float As[2][64][20];    // [stage][brow][k] (16 k + 4 pad)
    __shared__ float Bs[2][128][20];   // [stage][jrow][k]
    int tid = threadIdx.x;
    int j0 = blockIdx.x * 128, b0 = blockIdx.y * 64, ks = blockIdx.z;
    int k_base = ks * 192;
    int tx = tid & 15, ty = tid >> 4;

    // loader indices
    int arow = tid >> 2, ak4 = tid & 3;           // A: 1 float4/thread
    int bj0 = tid >> 2, bk4 = tid & 3;            // B: 2 float4/thread (rows bj0, bj0+64)
    const float* axrow = g_xcat + (size_t)(b0 + arow) * 768;

    unsigned long long acc[4][8];
#pragma unroll
    for (int i = 0; i < 4; i++)
#pragma unroll
        for (int j = 0; j < 8; j++) acc[i][j] = 0ull;

    float4 fa, fb0, fb1;
    // prefetch slab 0
    {
        int kg = k_base + ak4 * 4;
        fa = *(const float4*)(axrow + kg);
        int kgb = k_base + bk4 * 4;
        int j1 = j0 + bj0, j2 = j0 + bj0 + 64;
        fb0 = *(const float4*)((kgb < 256) ? (Wih + (size_t)j1 * 256 + kgb) : (Whh + (size_t)j1 * 512 + kgb - 256));
        fb1 = *(const float4*)((kgb < 256) ? (Wih + (size_t)j2 * 256 + kgb) : (Whh + (size_t)j2 * 512 + kgb - 256));
    }
    *(float4*)&As[0][arow][ak4 * 4] = fa;
    *(float4*)&Bs[0][bj0][bk4 * 4] = fb0;
    *(float4*)&Bs[0][bj0 + 64][bk4 * 4] = fb1;
    __syncthreads();

    for (int s = 0; s < 12; s++) {
        int cur = s & 1;
        if (s + 1 < 12) {
            int kg = k_base + (s + 1) * 16 + ak4 * 4;
            fa = *(const float4*)(axrow + kg);
            int kgb = k_base + (s + 1) * 16 + bk4 * 4;
            int j1 = j0 + bj0, j2 = j0 + bj0 + 64;
            fb0 = *(const float4*)((kgb < 256) ? (Wih + (size_t)j1 * 256 + kgb) : (Whh + (size_t)j1 * 512 + kgb - 256));
            fb1 = *(const float4*)((kgb < 256) ? (Wih + (size_t)j2 * 256 + kgb) : (Whh + (size_t)j2 * 512 + kgb - 256));
        }
        const float* As_ = &As[cur][0][0];
        const float* Bs_ = &Bs[cur][0][0];
#pragma unroll
        for (int kg = 0; kg < 4; kg++) {
            ulonglong2 au[4];
#pragma unroll
            for (int i = 0; i < 4; i++)
                au[i] = *(const ulonglong2*)(As_ + (ty * 4 + i) * 20 + kg * 4);
#pragma unroll
            for (int jj = 0; jj < 8; jj++) {
                ulonglong2 bu = *(const ulonglong2*)(Bs_ + (tx + 16 * jj) * 20 + kg * 4);
#pragma unroll
                for (int i = 0; i < 4; i++) {
                    ffma2(acc[i][jj], au[i].x, bu.x);
                    ffma2(acc[i][jj], au[i].y, bu.y);
                }
            }
        }
        if (s + 1 < 12) {
            int nxt = (s + 1) & 1;
            *(float4*)&As[nxt][arow][ak4 * 4] = fa;
            *(float4*)&Bs[nxt][bj0][bk4 * 4] = fb0;
            *(float4*)&Bs[nxt][bj0 + 64][bk4 * 4] = fb1;
        }
        __syncthreads();
    }

    float* outp = g_gates4 + (size_t)ks * B_ * 2048;
#pragma unroll
    for (int i = 0; i < 4; i++) {
        int row = (b0 + ty * 4 + i) * 2048 + j0 + tx;
#pragma unroll
        for (int jj = 0; jj < 8; jj++) {
            U64F2 u; u.u = acc[i][jj];
            outp[row + 16 * jj] = u.f.x + u.f.y;
        }
    }
}

// ---------------- K1b: sum partials + LSTM elementwise ----------------
__global__ void k1b_lstm(const float* __restrict__ blstm,
                         const float* __restrict__ prev_c,
                         float* __restrict__ dout) {
    int idx = blockIdx.x * 256 + threadIdx.x;
    int b = idx >> 9, hh = idx & 511;
    float gi = blstm[hh], gf = blstm[512 + hh], gg = blstm[1024 + hh], go = blstm[1536 + hh];
#pragma unroll
    for (int p = 0; p < 4; p++) {
        const float* gr = g_gates4 + (size_t)p * B_ * 2048 + b * 2048;
        gi += gr[hh]; gf += gr[512 + hh]; gg += gr[1024 + hh]; go += gr[1536 + hh];
    }
    float c = sigf(gf) * prev_c[idx] + sigf(gi) * tanhf(gg);
    float h = sigf(go) * tanhf(c);
    dout[OFF_C + idx] = c;
    dout[OFF_H + idx] = h;
}

// ---------------- K2: head-param GEMM, split-k=4 ----------------
__global__ void __launch_bounds__(256) k2_p(const float* __restrict__ readW,
                                            const float* __restrict__ writeW,
                                            const float* __restrict__ dout) {
    __shared__ float Hst[64][34];
    __shared__ float Wst[64][34];
    int tid = threadIdx.x;
    int c0 = blockIdx.x * 32, b0 = blockIdx.y * 32, ks = blockIdx.z;
    int kofs = ks * 128;
    int tx = tid & 15, ty = tid >> 4;
    int lr = tid >> 3, lk8 = (tid & 7) * 8;
    const float* hrow = dout + OFF_H + (b0 + lr) * 512 + kofs;
    int col_l = c0 + lr;
    const float* wrow = 0;
    if (col_l < 140) wrow = readW + col_l * 512 + kofs;
    else if (col_l < 338) wrow = writeW + (col_l - 140) * 512 + kofs;

    float acc[2][2] = {};
    float4 ph0, ph1, pw0, pw1;
    ph0 = *(const float4*)(hrow + lk8);
    ph1 = *(const float4*)(hrow + lk8 + 4);
    pw0 = wrow ? *(const float4*)(wrow + lk8) : make_float4(0.f, 0.f, 0.f, 0.f);
    pw1 = wrow ? *(const float4*)(wrow + lk8 + 4) : make_float4(0.f, 0.f, 0.f, 0.f);

    for (int kt = 0; kt < 2; kt++) {
#pragma unroll
        for (int i = 0; i < 4; i++) {
            Hst[lk8 + i][lr] = (&ph0.x)[i];
            Hst[lk8 + 4 + i][lr] = (&ph1.x)[i];
            Wst[lk8 + i][lr] = (&pw0.x)[i];
            Wst[lk8 + 4 + i][lr] = (&pw1.x)[i];
        }
        __syncthreads();
        if (kt + 1 < 2) {
            int kb = 64;
            ph0 = *(const float4*)(hrow + kb + lk8);
            ph1 = *(const float4*)(hrow + kb + lk8 + 4);
            pw0 = wrow ? *(const float4*)(wrow + kb + lk8) : make_float4(0.f, 0.f, 0.f, 0.f);
            pw1 = wrow ? *(const float4*)(wrow + kb + lk8 + 4) : make_float4(0.f, 0.f, 0.f, 0.f);
        }
#pragma unroll
        for (int kk = 0; kk < 64; kk++) {
            float2 h2 = *(const float2*)&Hst[kk][ty * 2];
            float2 w2 = *(const float2*)&Wst[kk][tx * 2];
            acc[0][0] = fmaf(h2.x, w2.x, acc[0][0]); acc[0][1] = fmaf(h2.x, w2.y, acc[0][1]);
            acc[1][0] = fmaf(h2.y, w2.x, acc[1][0]); acc[1][1] = fmaf(h2.y, w2.y, acc[1][1]);
        }
        __syncthreads();
    }
    float* outp = g_p4 + (size_t)ks * B_ * 352;
#pragma unroll
    for (int i = 0; i < 2; i++)
#pragma unroll
        for (int j = 0; j < 2; j++) {
            int col = c0 + tx * 2 + j;
            if (col < 338)
                outp[(b0 + ty * 2 + i) * 352 + col] = acc[i][j];
        }
}

// ---------------- block reductions (512 threads) ----------------
__device__ __forceinline__ float blk_red_sum(float v, volatile float* red) {
    int lane = threadIdx.x & 31, w = threadIdx.x >> 5;
#pragma unroll
    for (int o = 16; o; o >>= 1) v += __shfl_xor_sync(0xffffffffu, v, o);
    if (lane == 0) red[w] = v;
    __syncthreads();
    if (w == 0) {
        float x = (lane < 16) ? red[lane] : 0.0f;
#pragma unroll
        for (int o = 8; o; o >>= 1) x += __shfl_xor_sync(0xffffffffu, x, o);
        if (lane == 0) red[0] = x;
    }
    __syncthreads();
    float r = red[0];
    __syncthreads();
    return r;
}
__device__ __forceinline__ float blk_red_max(float v, volatile float* red) {
    int lane = threadIdx.x & 31, w = threadIdx.x >> 5;
#pragma unroll
    for (int o = 16; o; o >>= 1) v = fmaxf(v, __shfl_xor_sync(0xffffffffu, v, o));
    if (lane == 0) red[w] = v;
    __syncthreads();
    if (w == 0) {
        float x = (lane < 16) ? red[lane] : -3.0e38f;
#pragma unroll
        for (int o = 8; o; o >>= 1) x = fmaxf(x, __shfl_xor_sync(0xffffffffu, x, o));
        if (lane == 0) red[0] = x;
    }
    __syncthreads();
    float r = red[0];
    __syncthreads();
    return r;
}

// sum 4 split-k partials of head params
__device__ __forceinline__ float Psum(int b, int col) {
    float v = g_p4[(size_t)b * 352 + col];
    v += g_p4[(size_t)B_ * 352 + b * 352 + col];
    v += g_p4[(size_t)2 * B_ * 352 + b * 352 + col];
    v += g_p4[(size_t)3 * B_ * 352 + b * 352 + col];
    return v;
}

// ---------------- K34: fused addressing + read/write (one block per b, 2/SM) ----------------
__global__ void __launch_bounds__(512, 2) k34_fused(const float* __restrict__ mem,
                                                    const float* __restrict__ prev_ws,
                                                    const float* __restrict__ readb,
                                                    const float* __restrict__ writeb,
                                                    float* __restrict__ dout) {
    __shared__ float sim_s[3 * 2048];   // sims, then reused as final weights
    __shared__ float wgs[2048];         // gated weights, then partial-read buffer
    __shared__ float ksm[3 * 64];
    __shared__ float red[16];
    __shared__ float hp[3][6];
    __shared__ __align__(16) float es[64];
    __shared__ __align__(16) float as_[64];
    int b = blockIdx.x;
    int tid = threadIdx.x;
    int lane = tid & 31, wrp = tid >> 5;

    // ---- prologue: sum split-k partials + bias + activations ----
    if (tid < 192) {
        int h = tid >> 6, m = tid & 63;
        int base = (h < 2) ? h * 70 : 140;
        float bias = (h < 2) ? readb[base + m] : writeb[m];
        ksm[h * 64 + m] = tanhf(Psum(b, base + m) + bias);
    } else if (tid >= 320 && tid < 384) {
        int t = tid - 320;
        es[t] = sigf(Psum(b, 210 + t) + writeb[70 + t]);
    } else if (tid >= 384 && tid < 448) {
        int t = tid - 384;
        as_[t] = Psum(b, 274 + t) + writeb[134 + t];
    }
    if (tid < 3) {
        int h = tid;
        int base = (h < 2) ? h * 70 : 140;
        const float* bb = (h < 2) ? (readb + base) : writeb;
        float p64 = Psum(b, base + 64) + bb[64];
        float p65 = Psum(b, base + 65) + bb[65];
        float q0 = Psum(b, base + 66) + bb[66];
        float q1 = Psum(b, base + 67) + bb[67];
        float q2 = Psum(b, base + 68) + bb[68];
        float p69 = Psum(b, base + 69) + bb[69];
        hp[h][0] = softplusf(p64);
        hp[h][1] = sigf(p65);
        float mx = fmaxf(q0, fmaxf(q1, q2));
        float e0 = expf(q0 - mx), e1 = expf(q1 - mx), e2 = expf(q2 - mx);
        float si = 1.0f / (e0 + e1 + e2);
        hp[h][2] = e0 * si; hp[h][3] = e1 * si; hp[h][4] = e2 * si;
        hp[h][5] = 1.0f + softplusf(p69);
    }
    __syncthreads();

    // ---- phase B: stream memory, cosine sims (8 lanes per row) ----
    int q = lane >> 3, s = lane & 7, m0 = s * 8;
    float kreg[3][8];
#pragma unroll
    for (int h = 0; h < 3; h++)
#pragma unroll
        for (int i = 0; i < 8; i++) kreg[h][i] = ksm[h * 64 + m0 + i];
    float kn[3];
#pragma unroll
    for (int h = 0; h < 3; h++) {
        float sq = 0.f;
#pragma unroll
        for (int i = 0; i < 8; i++) sq = fmaf(kreg[h][i], kreg[h][i], sq);
        sq += __shfl_xor_sync(0xffffffffu, sq, 1);
        sq += __shfl_xor_sync(0xffffffffu, sq, 2);
        sq += __shfl_xor_sync(0xffffffffu, sq, 4);
        kn[h] = sqrtf(sq);
    }

    const float* mb = mem + (size_t)b * N_ * M_;
    for (int it = 0; it < 32; it += 2) {
        int na = it * 64 + wrp * 4 + q;
        int nb2 = na + 64;
        float4 va0 = *(const float4*)(mb + na * 64 + m0);
        float4 va1 = *(const float4*)(mb + na * 64 + m0 + 4);
        float4 vb0 = *(const float4*)(mb + nb2 * 64 + m0);
        float4 vb1 = *(const float4*)(mb + nb2 * 64 + m0 + 4);
#pragma unroll
        for (int half = 0; half < 2; half++) {
            float4 v0 = half ? vb0 : va0;
            float4 v1 = half ? vb1 : va1;
            int n = half ? nb2 : na;
            float d0 = 0.f, d1 = 0.f, d2 = 0.f, ss = 0.f;
#pragma unroll
            for (int j = 0; j < 8; j++) {
                float x = (j < 4) ? (&v0.x)[j] : (&v1.x)[j - 4];
                d0 = fmaf(kreg[0][j], x, d0);
                d1 = fmaf(kreg[1][j], x, d1);
                d2 = fmaf(kreg[2][j], x, d2);
                ss = fmaf(x, x, ss);
            }
            d0 += __shfl_xor_sync(0xffffffffu, d0, 1); d0 += __shfl_xor_sync(0xffffffffu, d0, 2); d0 += __shfl_xor_sync(0xffffffffu, d0, 4);
            d1 += __shfl_xor_sync(0xffffffffu, d1, 1); d1 += __shfl_xor_sync(0xffffffffu, d1, 2); d1 += __shfl_xor_sync(0xffffffffu, d1, 4);
            d2 += __shfl_xor_sync(0xffffffffu, d2, 1); d2 += __shfl_xor_sync(0xffffffffu, d2, 2); d2 += __shfl_xor_sync(0xffffffffu, d2, 4);
            ss += __shfl_xor_sync(0xffffffffu, ss, 1); ss += __shfl_xor_sync(0xffffffffu, ss, 2); ss += __shfl_xor_sync(0xffffffffu, ss, 4);
            if (s == 0) {
                float mn = sqrtf(ss);
                sim_s[0 * 2048 + n] = d0 / (kn[0] * mn + EPS_);
                sim_s[1 * 2048 + n] = d1 / (kn[1] * mn + EPS_);
                sim_s[2 * 2048 + n] = d2 / (kn[2] * mn + EPS_);
            }
        }
    }
    __syncthreads();

    // ---- phase C: softmax / interpolate / shift / sharpen ----
    for (int h = 0; h < 3; h++) {
        float beta = hp[h][0], g = hp[h][1];
        float s0 = hp[h][2], s1 = hp[h][3], s2 = hp[h][4], gamma = hp[h][5];
        float z[4], lm = -3.0e38f;
#pragma unroll
        for (int j = 0; j < 4; j++) {
            int n = tid + j * 512;
            z[j] = beta * sim_s[h * 2048 + n];
            lm = fmaxf(lm, z[j]);
        }
        float mx = blk_red_max(lm, red);
        float ex[4], lsum = 0.f;
#pragma unroll
        for (int j = 0; j < 4; j++) { ex[j] = expf(z[j] - mx); lsum += ex[j]; }
        float S = blk_red_sum(lsum, red);
        float invS = 1.0f / S;
        const float* pwb = prev_ws + ((size_t)h * B_ + b) * N_;
#pragma unroll
        for (int j = 0; j < 4; j++) {
            int n = tid + j * 512;
            wgs[n] = fmaf(g, ex[j] * invS, (1.0f - g) * pwb[n]);
        }
        __syncthreads();
        float wp4[4], psum = 0.f;
#pragma unroll
        for (int j = 0; j < 4; j++) {
            int n = tid + j * 512;
            float wt = s0 * wgs[(n + 2047) & 2047] + s1 * wgs[n] + s2 * wgs[(n + 1) & 2047];
            wp4[j] = powf(wt + EPS_, gamma);
            psum += wp4[j];
        }
        float S2 = blk_red_sum(psum, red);
        float inv2 = 1.0f / (S2 + EPS_);
        float* wout = dout + OFF_W + ((size_t)h * B_ + b) * N_;
#pragma unroll
        for (int j = 0; j < 4; j++) {
            int n = tid + j * 512;
            float wv = wp4[j] * inv2;
            wout[n] = wv;
            sim_s[h * 2048 + n] = wv;
        }
        __syncthreads();
    }

    // ---- phase D: memory write + weighted reads ----
    int hl = lane >> 4, lm2 = lane & 15;
    float4 e4 = *(const float4*)&es[lm2 * 4];
    float4 a4 = *(const float4*)&as_[lm2 * 4];
    float racc0[4] = {0.f, 0.f, 0.f, 0.f};
    float racc1[4] = {0.f, 0.f, 0.f, 0.f};
    const float4* msrc = (const float4*)(mem + (size_t)b * N_ * M_);
    float4* mdst = (float4*)(dout + OFF_MEM + (size_t)b * N_ * M_);

    for (int i = 0; i < 64; i += 4) {
        float4 v[4]; float w0[4], w1[4], ww[4]; int nn[4];
#pragma unroll
        for (int u = 0; u < 4; u++) {
            int n = wrp * 128 + 2 * (i + u) + hl;
            nn[u] = n;
            v[u] = __ldcs(&msrc[n * 16 + lm2]);
            w0[u] = sim_s[n]; w1[u] = sim_s[2048 + n]; ww[u] = sim_s[4096 + n];
        }
#pragma unroll
        for (int u = 0; u < 4; u++) {
            float4 nv;
            nv.x = fmaf(v[u].x, fmaf(-ww[u], e4.x, 1.0f), ww[u] * a4.x);
            nv.y = fmaf(v[u].y, fmaf(-ww[u], e4.y, 1.0f), ww[u] * a4.y);
            nv.z = fmaf(v[u].z, fmaf(-ww[u], e4.z, 1.0f), ww[u] * a4.z);
            nv.w = fmaf(v[u].w, fmaf(-ww[u], e4.w, 1.0f), ww[u] * a4.w);
            __stcs(&mdst[nn[u] * 16 + lm2], nv);
            racc0[0] = fmaf(w0[u], v[u].x, racc0[0]);
            racc0[1] = fmaf(w0[u], v[u].y, racc0[1]);
            racc0[2] = fmaf(w0[u], v[u].z, racc0[2]);
            racc0[3] = fmaf(w0[u], v[u].w, racc0[3]);
            racc1[0] = fmaf(w1[u], v[u].x, racc1[0]);
            racc1[1] = fmaf(w1[u], v[u].y, racc1[1]);
            racc1[2] = fmaf(w1[u], v[u].z, racc1[2]);
            racc1[3] = fmaf(w1[u], v[u].w, racc1[3]);
        }
    }
#pragma unroll
    for (int u = 0; u < 4; u++) {
        racc0[u] += __shfl_xor_sync(0xffffffffu, racc0[u], 16);
        racc1[u] += __shfl_xor_sync(0xffffffffu, racc1[u], 16);
    }
    __syncthreads();
    if (lane < 16) {
#pragma unroll
        for (int u = 0; u < 4; u++) {
            wgs[wrp * 128 + lm2 * 4 + u] = racc0[u];
            wgs[wrp * 128 + 64 + lm2 * 4 + u] = racc1[u];
        }
    }
    __syncthreads();
    if (tid < 128) {
        int h = tid >> 6, m = tid & 63;
        float sum = 0.f;
#pragma unroll
        for (int w = 0; w < 16; w++) sum += wgs[w * 128 + h * 64 + m];
        dout[OFF_READS + h * B_ * M_ + b * M_ + m] = sum;
    }
}

// ---------------- K5: output GEMM + sigmoid (4 b per block) ----------------
__global__ void __launch_bounds__(256) k5_out(const float* __restrict__ outW,
                                              const float* __restrict__ outb,
                                              float* __restrict__ dout) {
    __shared__ float Wst[128][68];
    __shared__ float xs[4][644];
    int tid = threadIdx.x;
    int b0 = blockIdx.x * 4;
    int o = tid & 127, half = tid >> 7;
    int lr = tid >> 1, c8 = (tid & 1) * 32;

    for (int idx = tid; idx < 4 * 640; idx += 256) {
        int bb = idx / 640, k = idx - bb * 640;
        int b = b0 + bb;
        float v;
        if (k < 512) v = dout[OFF_H + b * 512 + k];
        else if (k < 576) v = dout[OFF_READS + b * 64 + (k - 512)];
        else v = dout[OFF_READS + B_ * M_ + b * 64 + (k - 576)];
        xs[bb][k] = v;
    }

    float acc0 = 0.f, acc1 = 0.f;
    float4 pw[8];
#pragma unroll
    for (int i = 0; i < 8; i++) pw[i] = *(const float4*)(outW + lr * 640 + c8 + 4 * i);
    for (int kt = 0; kt < 10; kt++) {
        __syncthreads();
#pragma unroll
        for (int i = 0; i < 8; i++) *(float4*)&Wst[lr][c8 + 4 * i] = pw[i];
        __syncthreads();
        if (kt + 1 < 10) {
            int kb = (kt + 1) * 64;
#pragma unroll
            for (int i = 0; i < 8; i++) pw[i] = *(const float4*)(outW + lr * 640 + kb + c8 + 4 * i);
        }
        int kb = kt * 64;
#pragma unroll
        for (int k4 = 0; k4 < 16; k4++) {
            float4 wv = *(const float4*)&Wst[o][k4 * 4];
            float4 x0 = *(const float4*)&xs[half][kb + k4 * 4];
            float4 x1 = *(const float4*)&xs[half + 2][kb + k4 * 4];
            acc0 = fmaf(wv.x, x0.x, fmaf(wv.y, x0.y, fmaf(wv.z, x0.z, fmaf(wv.w, x0.w, acc0))));
            acc1 = fmaf(wv.x, x1.x, fmaf(wv.y, x1.y, fmaf(wv.z, x1.z, fmaf(wv.w, x1.w, acc1))));
        }
    }
    float bo = outb[o];
    dout[OFF_OUT + (b0 + half) * 128 + o] = sigf(acc0 + bo);
    dout[OFF_OUT + (b0 + half + 2) * 128 + o] = sigf(acc1 + bo);
}

extern "C" void kernel_launch(void* const* d_in, const int* in_sizes, int n_in,
                              void* d_out, int out_size) {
    const float* inp        = (const float*)d_in[0];
    const float* prev_reads = (const float*)d_in[1];
    const float* prev_h     = (const float*)d_in[2];
    const float* prev_c     = (const float*)d_in[3];
    const float* prev_ws    = (const float*)d_in[4];
    const float* memory     = (const float*)d_in[5];
    const float* W_ih       = (const float*)d_in[6];
    const float* W_hh       = (const float*)d_in[7];
    const float* b_lstm     = (const float*)d_in[8];
    const float* read_W     = (const float*)d_in[9];
    const float* read_b     = (const float*)d_in[10];
    const float* write_W    = (const float*)d_in[11];
    const float* write_b    = (const float*)d_in[12];
    const float* out_W      = (const float*)d_in[13];
    const float* out_b      = (const float*)d_in[14];
    float* dout = (float*)d_out;

    k0_pack<<<768, 256>>>(inp, prev_reads, prev_h);
    k1_gates<<<dim3(16, 4, 4), 256>>>(W_ih, W_hh);
    k1b_lstm<<<512, 256>>>(b_lstm, prev_c, dout);
    k2_p<<<dim3(11, 8, 4), 256>>>(read_W, write_W, dout);
    k34_fused<<<256, 512>>>(memory, prev_ws, read_b, write_b, dout);
    k5_out<<<64, 256>>>(out_W, out_b, dout);
}